// round 1
// baseline (speedup 1.0000x reference)
#include <cuda_runtime.h>
#include <math.h>

// Problem constants (fixed by setup_inputs)
#define NB 16
#define NP 32768
#define NG 128
#define TG 8          // truths per block
#define TK 4          // top-k (expand_num)
#define NTHREADS 128
#define NWARPS (NTHREADS / 32)

// Strict total order: value descending, index ascending (matches jax.lax.top_k
// stable tie-break).
__device__ __forceinline__ bool better(float av, int ai, float bv, int bi) {
    return (av > bv) || (av == bv && ai < bi);
}

__device__ __forceinline__ void ce(float &av, int &ai, float &bv, int &bi) {
    if (!better(av, ai, bv, bi)) {
        float tv = av; av = bv; bv = tv;
        int   ti = ai; ai = bi; bi = ti;
    }
}

// Merge my sorted-desc top-4 list (v,ix) with partner's sorted-desc list
// (pv,pix); keep the merged top-4 in (v,ix). Bitonic: reverse partner,
// concat (desc-then-asc = bitonic), split, sort top half. 8 compare-exchanges,
// fully unrolled, no dynamic register indexing.
__device__ __forceinline__ void merge4(float v[TK], int ix[TK],
                                       const float pv[TK], const int pix[TK]) {
    float s4 = pv[3], s5 = pv[2], s6 = pv[1], s7 = pv[0];
    int   t4 = pix[3], t5 = pix[2], t6 = pix[1], t7 = pix[0];
    ce(v[0], ix[0], s4, t4);
    ce(v[1], ix[1], s5, t5);
    ce(v[2], ix[2], s6, t6);
    ce(v[3], ix[3], s7, t7);
    ce(v[0], ix[0], v[2], ix[2]);
    ce(v[1], ix[1], v[3], ix[3]);
    ce(v[0], ix[0], v[1], ix[1]);
    ce(v[2], ix[2], v[3], ix[3]);
}

__global__ __launch_bounds__(NTHREADS)
void ptl_offset_kernel(const float* __restrict__ rois,
                       const float* __restrict__ targets,
                       float* __restrict__ out) {
    const int blk = blockIdx.x;                 // 0..NB*(NG/TG)-1
    const int b   = blk / (NG / TG);
    const int g0  = (blk % (NG / TG)) * TG;
    const int tid = threadIdx.x;

    __shared__ float s_t[TG][5];        // x1,y1,x2,y2,area
    __shared__ float s_wv[NWARPS][TK];
    __shared__ int   s_wi[NWARPS][TK];
    __shared__ int   s_sel[TG][TK];

    // Stage truth boxes
    if (tid < TG * 4) {
        int g = tid >> 2, c = tid & 3;
        s_t[g][c] = targets[((size_t)b * NG + (g0 + g)) * 4 + c];
    }
    __syncthreads();
    if (tid < TG) {
        // area_t, rounded once and reused (matches jax broadcast)
        s_t[tid][4] = __fmul_rn(s_t[tid][2] - s_t[tid][0],
                                s_t[tid][3] - s_t[tid][1]);
    }
    __syncthreads();

    // Truths into registers
    float tx1[TG], ty1[TG], tx2[TG], ty2[TG], tar[TG];
#pragma unroll
    for (int g = 0; g < TG; g++) {
        tx1[g] = s_t[g][0]; ty1[g] = s_t[g][1];
        tx2[g] = s_t[g][2]; ty2[g] = s_t[g][3];
        tar[g] = s_t[g][4];
    }

    // Per-thread sorted-desc top-4 lists
    float lv[TG][TK];
    int   li[TG][TK];
#pragma unroll
    for (int g = 0; g < TG; g++)
#pragma unroll
        for (int j = 0; j < TK; j++) { lv[g][j] = -1e30f; li[g][j] = 0x7fffffff; }

    const float4* pri = (const float4*)(rois + ((size_t)b * 2 + 1) * (size_t)NP * 4);

#pragma unroll 2
    for (int p = tid; p < NP; p += NTHREADS) {
        float4 pr = __ldg(&pri[p]);
        float area_p = __fmul_rn(pr.z - pr.x, pr.w - pr.y);  // rounded once (jax)
#pragma unroll
        for (int g = 0; g < TG; g++) {
            float lx = fmaxf(tx1[g], pr.x);
            float ly = fmaxf(ty1[g], pr.y);
            float rx = fminf(tx2[g], pr.z);
            float ry = fminf(ty2[g], pr.w);
            float w  = fmaxf(rx - lx, 0.0f);
            float h  = fmaxf(ry - ly, 0.0f);
            float inter = __fmul_rn(w, h);                   // block FMA contraction
            float denom = (tar[g] + area_p) - inter;
            // Division-free conservative gate: rd(product) <= real product, so
            // a candidate whose exact rn-quotient beats lv[g][3] always passes.
            if (inter > __fmul_rd(lv[g][3], denom)) {
                float q = __fdiv_rn(inter, denom);           // exact IEEE, = jax bits
                if (q > lv[g][3]) {                          // strict: earlier index wins ties
                    if (q > lv[g][2]) {
                        lv[g][3] = lv[g][2]; li[g][3] = li[g][2];
                        if (q > lv[g][1]) {
                            lv[g][2] = lv[g][1]; li[g][2] = li[g][1];
                            if (q > lv[g][0]) {
                                lv[g][1] = lv[g][0]; li[g][1] = li[g][0];
                                lv[g][0] = q; li[g][0] = p;
                            } else { lv[g][1] = q; li[g][1] = p; }
                        } else { lv[g][2] = q; li[g][2] = p; }
                    } else { lv[g][3] = q; li[g][3] = p; }
                }
            }
        }
    }

    const int lane = tid & 31;
    const int wid  = tid >> 5;

    // Block-wide top-4 reduction, one truth at a time
#pragma unroll 1
    for (int g = 0; g < TG; g++) {
        float v[TK]; int ix[TK];
#pragma unroll
        for (int j = 0; j < TK; j++) { v[j] = lv[g][j]; ix[j] = li[g][j]; }

        // Intra-warp tree merge
#pragma unroll
        for (int off = 16; off >= 1; off >>= 1) {
            float pv[TK]; int pix[TK];
#pragma unroll
            for (int j = 0; j < TK; j++) {
                pv[j]  = __shfl_down_sync(0xffffffffu, v[j],  off);
                pix[j] = __shfl_down_sync(0xffffffffu, ix[j], off);
            }
            merge4(v, ix, pv, pix);
        }
        if (lane == 0) {
#pragma unroll
            for (int j = 0; j < TK; j++) { s_wv[wid][j] = v[j]; s_wi[wid][j] = ix[j]; }
        }
        __syncthreads();
        if (wid == 0) {
            int src = (lane < NWARPS) ? lane : 0;
            float v2[TK]; int i2[TK];
#pragma unroll
            for (int j = 0; j < TK; j++) { v2[j] = s_wv[src][j]; i2[j] = s_wi[src][j]; }
#pragma unroll
            for (int off = 2; off >= 1; off >>= 1) {
                float pv[TK]; int pix[TK];
#pragma unroll
                for (int j = 0; j < TK; j++) {
                    pv[j]  = __shfl_down_sync(0xffffffffu, v2[j],  off);
                    pix[j] = __shfl_down_sync(0xffffffffu, i2[j], off);
                }
                merge4(v2, i2, pv, pix);
            }
            if (lane == 0) {
#pragma unroll
                for (int j = 0; j < TK; j++) s_sel[g][j] = i2[j];
            }
        }
        __syncthreads();
    }

    // Encode + store: TG*TK = 32 output rows for this block
    if (tid < TG * TK) {
        int g = tid >> 2, k = tid & 3;
        int p = s_sel[g][k];
        float4 pr = __ldg(&pri[p]);
        float pcx = (pr.x + pr.z) * 0.5f;
        float pcy = (pr.y + pr.w) * 0.5f;
        float pw  = pr.z - pr.x;
        float ph  = pr.w - pr.y;
        float gx1 = s_t[g][0], gy1 = s_t[g][1], gx2 = s_t[g][2], gy2 = s_t[g][3];
        float gcx = (gx1 + gx2) * 0.5f;
        float gcy = (gy1 + gy2) * 0.5f;
        float gw  = gx2 - gx1;
        float gh  = gy2 - gy1;
        float4 o;
        o.x = (gcx - pcx) / (0.1f * pw);
        o.y = (gcy - pcy) / (0.1f * ph);
        o.z = logf(gw / pw) / 0.2f;
        o.w = logf(gh / ph) / 0.2f;
        ((float4*)out)[((size_t)b * NG + (g0 + g)) * TK + k] = o;
    }
}

extern "C" void kernel_launch(void* const* d_in, const int* in_sizes, int n_in,
                              void* d_out, int out_size) {
    const float* rois    = (const float*)d_in[0];   // (16, 2, 32768, 4) f32
    const float* targets = (const float*)d_in[1];   // (16, 128, 4) f32
    float* out           = (float*)d_out;           // (16, 512, 4) f32
    (void)in_sizes; (void)n_in; (void)out_size;

    dim3 grid(NB * (NG / TG));
    dim3 block(NTHREADS);
    ptl_offset_kernel<<<grid, block>>>(rois, targets, out);
}

// round 3
// speedup vs baseline: 1.3746x; 1.3746x over previous
#include <cuda_runtime.h>
#include <math.h>

// Problem constants (fixed by setup_inputs)
#define NB 16
#define NP 32768
#define NG 128
#define TG 4          // truths per block
#define TK 4          // top-k (expand_num)
#define PSPLIT 4      // prior-dimension split
#define PCHUNK (NP / PSPLIT)       // 8192 priors per block
#define NTHREADS 128
#define NWARPS (NTHREADS / 32)
#define NBG (NB * NG)              // 2048 (b,g) pairs
#define NLISTS (PSPLIT * NWARPS)   // 16 partial top-4 lists per (b,g)

// Scratch for partial top-4 candidates, layout [(list*TK + k)][bg] so phase-2
// reads are coalesced across threads. 512KB + 512KB, statically allocated.
__device__ float g_cv[NLISTS * TK * NBG];
__device__ int   g_ci[NLISTS * TK * NBG];

// Strict total order: value descending, index ascending (matches jax.lax.top_k
// stable tie-break).
__device__ __forceinline__ bool better(float av, int ai, float bv, int bi) {
    return (av > bv) || (av == bv && ai < bi);
}

__device__ __forceinline__ void ce(float &av, int &ai, float &bv, int &bi) {
    if (!better(av, ai, bv, bi)) {
        float tv = av; av = bv; bv = tv;
        int   ti = ai; ai = bi; bi = ti;
    }
}

// Merge my sorted-desc top-4 (v,ix) with partner's sorted-desc (pv,pix).
// Bitonic merge, 8 compare-exchanges, fully unrolled.
__device__ __forceinline__ void merge4(float v[TK], int ix[TK],
                                       const float pv[TK], const int pix[TK]) {
    float s4 = pv[3], s5 = pv[2], s6 = pv[1], s7 = pv[0];
    int   t4 = pix[3], t5 = pix[2], t6 = pix[1], t7 = pix[0];
    ce(v[0], ix[0], s4, t4);
    ce(v[1], ix[1], s5, t5);
    ce(v[2], ix[2], s6, t6);
    ce(v[3], ix[3], s7, t7);
    ce(v[0], ix[0], v[2], ix[2]);
    ce(v[1], ix[1], v[3], ix[3]);
    ce(v[0], ix[0], v[1], ix[1]);
    ce(v[2], ix[2], v[3], ix[3]);
}

// ── Phase 1: per-chunk warp-level top-4 ─────────────────────────────────────
__global__ __launch_bounds__(NTHREADS, 4)
void ptl_phase1(const float* __restrict__ rois,
                const float* __restrict__ targets) {
    const int blk = blockIdx.x;                  // NB*(NG/TG)*PSPLIT blocks
    const int pc  = blk % PSPLIT;
    const int t   = blk / PSPLIT;
    const int b   = t / (NG / TG);
    const int g0  = (t % (NG / TG)) * TG;
    const int tid = threadIdx.x;

    __shared__ float s_t[TG][5];   // x1,y1,x2,y2,area_t

    if (tid < TG * 4) {
        int g = tid >> 2, c = tid & 3;
        s_t[g][c] = targets[((size_t)b * NG + (g0 + g)) * 4 + c];
    }
    __syncthreads();
    if (tid < TG) {
        s_t[tid][4] = __fmul_rn(s_t[tid][2] - s_t[tid][0],
                                s_t[tid][3] - s_t[tid][1]);
    }
    __syncthreads();

    float tx1[TG], ty1[TG], tx2[TG], ty2[TG], tar[TG];
#pragma unroll
    for (int g = 0; g < TG; g++) {
        tx1[g] = s_t[g][0]; ty1[g] = s_t[g][1];
        tx2[g] = s_t[g][2]; ty2[g] = s_t[g][3];
        tar[g] = s_t[g][4];
    }

    float lv[TG][TK];
    int   li[TG][TK];
#pragma unroll
    for (int g = 0; g < TG; g++)
#pragma unroll
        for (int j = 0; j < TK; j++) { lv[g][j] = -1e30f; li[g][j] = 0x7fffffff; }

    const float4* pri = (const float4*)(rois + ((size_t)b * 2 + 1) * (size_t)NP * 4);
    const int p0 = pc * PCHUNK;

#pragma unroll 2
    for (int p = p0 + tid; p < p0 + PCHUNK; p += NTHREADS) {
        float4 pr = __ldg(&pri[p]);
        float area_p = __fmul_rn(pr.z - pr.x, pr.w - pr.y);
#pragma unroll
        for (int g = 0; g < TG; g++) {
            float lx = fmaxf(tx1[g], pr.x);
            float ly = fmaxf(ty1[g], pr.y);
            float rx = fminf(tx2[g], pr.z);
            float ry = fminf(ty2[g], pr.w);
            float w  = fmaxf(rx - lx, 0.0f);
            float h  = fmaxf(ry - ly, 0.0f);
            float inter = __fmul_rn(w, h);
            float denom = (tar[g] + area_p) - inter;
            // Conservative division-free gate: rd(product) <= exact product, so
            // anything whose exact rn-quotient beats lv[3] always passes.
            if (inter > __fmul_rd(lv[g][3], denom)) {
                float q = __fdiv_rn(inter, denom);     // exact IEEE, = jax bits
                if (q > lv[g][3]) {                    // strict: scan order = idx asc
                    if (q > lv[g][2]) {
                        lv[g][3] = lv[g][2]; li[g][3] = li[g][2];
                        if (q > lv[g][1]) {
                            lv[g][2] = lv[g][1]; li[g][2] = li[g][1];
                            if (q > lv[g][0]) {
                                lv[g][1] = lv[g][0]; li[g][1] = li[g][0];
                                lv[g][0] = q; li[g][0] = p;
                            } else { lv[g][1] = q; li[g][1] = p; }
                        } else { lv[g][2] = q; li[g][2] = p; }
                    } else { lv[g][3] = q; li[g][3] = p; }
                }
            }
        }
    }

    const int lane = tid & 31;
    const int wid  = tid >> 5;

    // Intra-warp tree merge; lane 0 of each warp writes its partial top-4.
#pragma unroll
    for (int g = 0; g < TG; g++) {
        float v[TK]; int ix[TK];
#pragma unroll
        for (int j = 0; j < TK; j++) { v[j] = lv[g][j]; ix[j] = li[g][j]; }
#pragma unroll
        for (int off = 16; off >= 1; off >>= 1) {
            float pv[TK]; int pix[TK];
#pragma unroll
            for (int j = 0; j < TK; j++) {
                pv[j]  = __shfl_down_sync(0xffffffffu, v[j],  off);
                pix[j] = __shfl_down_sync(0xffffffffu, ix[j], off);
            }
            merge4(v, ix, pv, pix);
        }
        if (lane == 0) {
            int bg = b * NG + g0 + g;
            int list = pc * NWARPS + wid;
#pragma unroll
            for (int j = 0; j < TK; j++) {
                g_cv[(list * TK + j) * NBG + bg] = v[j];
                g_ci[(list * TK + j) * NBG + bg] = ix[j];
            }
        }
    }
}

// ── Phase 2: merge 16 partial lists per (b,g), encode, store ────────────────
__global__ __launch_bounds__(NTHREADS)
void ptl_phase2(const float* __restrict__ rois,
                const float* __restrict__ targets,
                float* __restrict__ out) {
    const int bg = blockIdx.x * NTHREADS + threadIdx.x;   // 0..NBG-1
    const int b  = bg / NG;

    float lv[TK]; int li[TK];
#pragma unroll
    for (int j = 0; j < TK; j++) { lv[j] = -1e30f; li[j] = 0x7fffffff; }

    // Sequential insertion of all 64 candidates; full (v,idx) comparisons so
    // any processing order yields the jax.lax.top_k stable result.
#pragma unroll 4
    for (int c = 0; c < NLISTS * TK; c++) {
        float q  = g_cv[c * NBG + bg];
        int   qi = g_ci[c * NBG + bg];
        if (better(q, qi, lv[3], li[3])) {
            if (better(q, qi, lv[2], li[2])) {
                lv[3] = lv[2]; li[3] = li[2];
                if (better(q, qi, lv[1], li[1])) {
                    lv[2] = lv[1]; li[2] = li[1];
                    if (better(q, qi, lv[0], li[0])) {
                        lv[1] = lv[0]; li[1] = li[0];
                        lv[0] = q; li[0] = qi;
                    } else { lv[1] = q; li[1] = qi; }
                } else { lv[2] = q; li[2] = qi; }
            } else { lv[3] = q; li[3] = qi; }
        }
    }

    // Encode 4 rows
    float gx1 = targets[(size_t)bg * 4 + 0];
    float gy1 = targets[(size_t)bg * 4 + 1];
    float gx2 = targets[(size_t)bg * 4 + 2];
    float gy2 = targets[(size_t)bg * 4 + 3];
    float gcx = (gx1 + gx2) * 0.5f;
    float gcy = (gy1 + gy2) * 0.5f;
    float gw  = gx2 - gx1;
    float gh  = gy2 - gy1;

    const float4* pri = (const float4*)(rois + ((size_t)b * 2 + 1) * (size_t)NP * 4);
#pragma unroll
    for (int k = 0; k < TK; k++) {
        float4 pr = __ldg(&pri[li[k]]);
        float pcx = (pr.x + pr.z) * 0.5f;
        float pcy = (pr.y + pr.w) * 0.5f;
        float pw  = pr.z - pr.x;
        float ph  = pr.w - pr.y;
        float4 o;
        o.x = (gcx - pcx) / (0.1f * pw);
        o.y = (gcy - pcy) / (0.1f * ph);
        o.z = logf(gw / pw) / 0.2f;
        o.w = logf(gh / ph) / 0.2f;
        ((float4*)out)[(size_t)bg * TK + k] = o;
    }
}

extern "C" void kernel_launch(void* const* d_in, const int* in_sizes, int n_in,
                              void* d_out, int out_size) {
    const float* rois    = (const float*)d_in[0];   // (16, 2, 32768, 4) f32
    const float* targets = (const float*)d_in[1];   // (16, 128, 4) f32
    float* out           = (float*)d_out;           // (16, 512, 4) f32
    (void)in_sizes; (void)n_in; (void)out_size;

    ptl_phase1<<<NB * (NG / TG) * PSPLIT, NTHREADS>>>(rois, targets);
    ptl_phase2<<<NBG / NTHREADS, NTHREADS>>>(rois, targets, out);
}